// round 1
// baseline (speedup 1.0000x reference)
#include <cuda_runtime.h>
#include <cstdint>
#include <math.h>

// ---------------------------------------------------------------------------
// TokenPacker: 9x GEMM [Mx1024]@[1024x1024]^T + 3x LayerNorm + 4-key attention
// All tensors kept in natural (n, token, E) layout; _divide permutation is
// absorbed into attention key-row indexing. TF32 mma.sync GEMMs.
// ---------------------------------------------------------------------------

#define E_DIM   1024
#define N_IMG   64
#define NQ_TOK  144
#define TN_TOK  576
#define M_BIG   (N_IMG * TN_TOK)   // 36864
#define M_SMALL (N_IMG * NQ_TOK)   // 9216
#define NKT     64                 // K / BK = 1024/16

// Scratch (device statics; no cudaMalloc allowed)
__device__ float g_h  [(size_t)M_BIG   * E_DIM];
__device__ float g_key[(size_t)M_BIG   * E_DIM];
__device__ float g_val[(size_t)M_BIG   * E_DIM];
__device__ float g_kh [(size_t)M_BIG   * E_DIM];
__device__ float g_vh [(size_t)M_BIG   * E_DIM];
__device__ float g_q  [(size_t)M_SMALL * E_DIM];
__device__ float g_qh [(size_t)M_SMALL * E_DIM];
__device__ float g_o  [(size_t)M_SMALL * E_DIM];

__device__ __forceinline__ uint32_t f2tf32(float f) {
    uint32_t r;
    asm("cvt.rna.tf32.f32 %0, %1;" : "=r"(r) : "f"(f));
    return r;
}

__device__ __forceinline__ float gelu_exact(float x) {
    return 0.5f * x * (1.0f + erff(x * 0.70710678118654752f));
}

#define CP_ASYNC16(smem_u32, gptr) \
    asm volatile("cp.async.cg.shared.global [%0], [%1], 16;\n" :: "r"(smem_u32), "l"(gptr))

// ---------------------------------------------------------------------------
// GEMM: C[M x 1024] = act(A[M x 1024] @ W[1024 x 1024]^T + bias)
// ACT: 0 = none, 1 = exact GELU.  Tiles: 128x128x16, 256 threads, 8 warps
// (warp tile 64x32), mma.sync.m16n8k8.tf32, cp.async double buffer.
// M, N, K all exact multiples of tile dims -> no bounds checks.
// ---------------------------------------------------------------------------
template <int ACT>
__global__ __launch_bounds__(256, 2)
void gemm_tf32(const float* __restrict__ A, const float* __restrict__ W,
               const float* __restrict__ bias, float* __restrict__ C)
{
    __shared__ float As[2][128][20];   // stride 20 -> conflict-free frag loads
    __shared__ float Bs[2][128][20];

    const int tid  = threadIdx.x;
    const int warp = tid >> 5;
    const int lane = tid & 31;
    const int grp  = lane >> 2;   // 0..7
    const int tig  = lane & 3;    // 0..3
    const int wm   = (warp & 1) * 64;
    const int wn   = (warp >> 1) * 32;
    const int row0 = blockIdx.y * 128;
    const int col0 = blockIdx.x * 128;

    float acc[4][4][4];
    #pragma unroll
    for (int i = 0; i < 4; i++)
        #pragma unroll
        for (int j = 0; j < 4; j++)
            #pragma unroll
            for (int k = 0; k < 4; k++) acc[i][j][k] = 0.0f;

    // gmem->smem mapping: each thread copies 2 float4 per tile per matrix
    const int lr0 = tid >> 2;     // 0..63 (rows 0..63 for i=0, +64 for i=1)
    const int lc4 = tid & 3;      // float4 column 0..3 (16 floats per row)

    // prologue: stage 0, kt = 0
    {
        #pragma unroll
        for (int i = 0; i < 2; i++) {
            int r = lr0 + i * 64;
            CP_ASYNC16((uint32_t)__cvta_generic_to_shared(&As[0][r][lc4 * 4]),
                       A + (size_t)(row0 + r) * E_DIM + lc4 * 4);
            CP_ASYNC16((uint32_t)__cvta_generic_to_shared(&Bs[0][r][lc4 * 4]),
                       W + (size_t)(col0 + r) * E_DIM + lc4 * 4);
        }
        asm volatile("cp.async.commit_group;\n");
    }

    for (int kt = 0; kt < NKT; kt++) {
        const int s = kt & 1;
        if (kt + 1 < NKT) {
            const int ns = s ^ 1;
            const int ko = (kt + 1) * 16;
            #pragma unroll
            for (int i = 0; i < 2; i++) {
                int r = lr0 + i * 64;
                CP_ASYNC16((uint32_t)__cvta_generic_to_shared(&As[ns][r][lc4 * 4]),
                           A + (size_t)(row0 + r) * E_DIM + ko + lc4 * 4);
                CP_ASYNC16((uint32_t)__cvta_generic_to_shared(&Bs[ns][r][lc4 * 4]),
                           W + (size_t)(col0 + r) * E_DIM + ko + lc4 * 4);
            }
            asm volatile("cp.async.commit_group;\n");
            asm volatile("cp.async.wait_group 1;\n");
        } else {
            asm volatile("cp.async.wait_group 0;\n");
        }
        __syncthreads();

        #pragma unroll
        for (int ks = 0; ks < 2; ks++) {
            const int k0 = ks * 8;
            uint32_t af[4][4], bf[4][2];
            #pragma unroll
            for (int mi = 0; mi < 4; mi++) {
                int r = wm + mi * 16 + grp;
                af[mi][0] = f2tf32(As[s][r    ][k0 + tig]);
                af[mi][1] = f2tf32(As[s][r + 8][k0 + tig]);
                af[mi][2] = f2tf32(As[s][r    ][k0 + tig + 4]);
                af[mi][3] = f2tf32(As[s][r + 8][k0 + tig + 4]);
            }
            #pragma unroll
            for (int ni = 0; ni < 4; ni++) {
                int c = wn + ni * 8 + grp;
                bf[ni][0] = f2tf32(Bs[s][c][k0 + tig]);
                bf[ni][1] = f2tf32(Bs[s][c][k0 + tig + 4]);
            }
            #pragma unroll
            for (int mi = 0; mi < 4; mi++)
                #pragma unroll
                for (int ni = 0; ni < 4; ni++)
                    asm volatile(
                        "mma.sync.aligned.m16n8k8.row.col.f32.tf32.tf32.f32 "
                        "{%0,%1,%2,%3}, {%4,%5,%6,%7}, {%8,%9}, {%0,%1,%2,%3};\n"
                        : "+f"(acc[mi][ni][0]), "+f"(acc[mi][ni][1]),
                          "+f"(acc[mi][ni][2]), "+f"(acc[mi][ni][3])
                        : "r"(af[mi][0]), "r"(af[mi][1]), "r"(af[mi][2]), "r"(af[mi][3]),
                          "r"(bf[ni][0]), "r"(bf[ni][1]));
        }
        __syncthreads();
    }

    // epilogue: bias + activation, float2 stores
    #pragma unroll
    for (int ni = 0; ni < 4; ni++) {
        const int col = col0 + wn + ni * 8 + tig * 2;
        float bv0 = 0.0f, bv1 = 0.0f;
        if (bias) { bv0 = bias[col]; bv1 = bias[col + 1]; }
        #pragma unroll
        for (int mi = 0; mi < 4; mi++) {
            #pragma unroll
            for (int half = 0; half < 2; half++) {
                const int row = row0 + wm + mi * 16 + grp + half * 8;
                float v0 = acc[mi][ni][half * 2 + 0] + bv0;
                float v1 = acc[mi][ni][half * 2 + 1] + bv1;
                if (ACT == 1) { v0 = gelu_exact(v0); v1 = gelu_exact(v1); }
                *(float2*)(C + (size_t)row * E_DIM + col) = make_float2(v0, v1);
            }
        }
    }
}

// ---------------------------------------------------------------------------
// In-place LayerNorm over rows of 1024 (eps = 1e-6). One block (256 thr) / row.
// ---------------------------------------------------------------------------
__global__ void ln_kernel(float* __restrict__ data,
                          const float* __restrict__ w, const float* __restrict__ b)
{
    const int row = blockIdx.x;
    float4* p = (float4*)(data + (size_t)row * E_DIM);
    float4 v = p[threadIdx.x];
    float s = v.x + v.y + v.z + v.w;
    float q = v.x * v.x + v.y * v.y + v.z * v.z + v.w * v.w;
    #pragma unroll
    for (int o = 16; o; o >>= 1) {
        s += __shfl_xor_sync(0xffffffffu, s, o);
        q += __shfl_xor_sync(0xffffffffu, q, o);
    }
    __shared__ float ss[8], sq[8];
    const int warp = threadIdx.x >> 5, lane = threadIdx.x & 31;
    if (lane == 0) { ss[warp] = s; sq[warp] = q; }
    __syncthreads();
    if (warp == 0) {
        s = (lane < 8) ? ss[lane] : 0.0f;
        q = (lane < 8) ? sq[lane] : 0.0f;
        #pragma unroll
        for (int o = 4; o; o >>= 1) {
            s += __shfl_xor_sync(0xffffffffu, s, o);
            q += __shfl_xor_sync(0xffffffffu, q, o);
        }
        if (lane == 0) { ss[0] = s; sq[0] = q; }
    }
    __syncthreads();
    const float mean = ss[0] * (1.0f / 1024.0f);
    const float var  = sq[0] * (1.0f / 1024.0f) - mean * mean;
    const float rstd = rsqrtf(var + 1e-6f);
    const float4 wv = ((const float4*)w)[threadIdx.x];
    const float4 bv = ((const float4*)b)[threadIdx.x];
    v.x = (v.x - mean) * rstd * wv.x + bv.x;
    v.y = (v.y - mean) * rstd * wv.y + bv.y;
    v.z = (v.z - mean) * rstd * wv.z + bv.z;
    v.w = (v.w - mean) * rstd * wv.w + bv.w;
    p[threadIdx.x] = v;
}

// ---------------------------------------------------------------------------
// Attention: q len 1 attends over its 2x2 key patch. One block per output row
// r = n*144 + q; warp w handles head w (HD=128, 4 floats/lane).
// ---------------------------------------------------------------------------
__global__ void attn_kernel(const float* __restrict__ qh, const float* __restrict__ kh,
                            const float* __restrict__ vh, float* __restrict__ o)
{
    const int r  = blockIdx.x;
    const int n  = r / NQ_TOK;
    const int qi = r - n * NQ_TOK;
    const int ar = qi / 12;
    const int ac = qi - ar * 12;
    const int head = threadIdx.x >> 5, lane = threadIdx.x & 31;
    const size_t qoff = (size_t)r * E_DIM + head * 128 + lane * 4;
    const float4 qv = *(const float4*)(qh + qoff);

    int trow[4];
    #pragma unroll
    for (int j = 0; j < 4; j++)
        trow[j] = n * TN_TOK + (2 * ar + (j >> 1)) * 24 + (2 * ac + (j & 1));

    float s[4];
    #pragma unroll
    for (int j = 0; j < 4; j++) {
        const float4 kv = *(const float4*)(kh + (size_t)trow[j] * E_DIM + head * 128 + lane * 4);
        float d = qv.x * kv.x + qv.y * kv.y + qv.z * kv.z + qv.w * kv.w;
        #pragma unroll
        for (int off = 16; off; off >>= 1) d += __shfl_xor_sync(0xffffffffu, d, off);
        s[j] = d * 0.08838834764831843f;   // 1/sqrt(128)
    }
    const float m = fmaxf(fmaxf(s[0], s[1]), fmaxf(s[2], s[3]));
    float e[4], tot = 0.0f;
    #pragma unroll
    for (int j = 0; j < 4; j++) { e[j] = expf(s[j] - m); tot += e[j]; }
    const float inv = 1.0f / tot;

    float4 acc = make_float4(0.f, 0.f, 0.f, 0.f);
    #pragma unroll
    for (int j = 0; j < 4; j++) {
        const float p = e[j] * inv;
        const float4 vv = *(const float4*)(vh + (size_t)trow[j] * E_DIM + head * 128 + lane * 4);
        acc.x += p * vv.x; acc.y += p * vv.y; acc.z += p * vv.z; acc.w += p * vv.w;
    }
    *(float4*)(o + qoff) = acc;
}

// ---------------------------------------------------------------------------
extern "C" void kernel_launch(void* const* d_in, const int* in_sizes, int n_in,
                              void* d_out, int out_size)
{
    const float* x      = (const float*)d_in[0];
    const float* x_feat = (const float*)d_in[1];
    const float* w_q    = (const float*)d_in[2];
    const float* w_k1   = (const float*)d_in[3];
    const float* b_k1   = (const float*)d_in[4];
    const float* w_k2   = (const float*)d_in[5];
    const float* b_k2   = (const float*)d_in[6];
    const float* w_v1   = (const float*)d_in[7];
    const float* b_v1   = (const float*)d_in[8];
    const float* w_v2   = (const float*)d_in[9];
    const float* b_v2   = (const float*)d_in[10];
    const float* ln_q_w = (const float*)d_in[11];
    const float* ln_q_b = (const float*)d_in[12];
    const float* ln_k_w = (const float*)d_in[13];
    const float* ln_k_b = (const float*)d_in[14];
    const float* ln_v_w = (const float*)d_in[15];
    const float* ln_v_b = (const float*)d_in[16];
    const float* in_w   = (const float*)d_in[17];
    const float* in_b   = (const float*)d_in[18];
    const float* out_w  = (const float*)d_in[19];
    const float* out_b  = (const float*)d_in[20];

    float *h, *key, *val, *kh, *vh, *qb, *qh, *o;
    cudaGetSymbolAddress((void**)&h,   g_h);
    cudaGetSymbolAddress((void**)&key, g_key);
    cudaGetSymbolAddress((void**)&val, g_val);
    cudaGetSymbolAddress((void**)&kh,  g_kh);
    cudaGetSymbolAddress((void**)&vh,  g_vh);
    cudaGetSymbolAddress((void**)&qb,  g_q);
    cudaGetSymbolAddress((void**)&qh,  g_qh);
    cudaGetSymbolAddress((void**)&o,   g_o);

    const dim3 blk(256);
    const dim3 gBig(8, M_BIG / 128);    // (8, 288)
    const dim3 gSm(8, M_SMALL / 128);   // (8, 72)

    // K path: gelu(x_feat @ w_k1^T + b) @ w_k2^T + b -> LN
    gemm_tf32<1><<<gBig, blk>>>(x_feat, w_k1, b_k1, h);
    gemm_tf32<0><<<gBig, blk>>>(h, w_k2, b_k2, key);
    ln_kernel<<<M_BIG, 256>>>(key, ln_k_w, ln_k_b);
    // V path
    gemm_tf32<1><<<gBig, blk>>>(x_feat, w_v1, b_v1, h);
    gemm_tf32<0><<<gBig, blk>>>(h, w_v2, b_v2, val);
    ln_kernel<<<M_BIG, 256>>>(val, ln_v_w, ln_v_b);
    // Q path (no bias on w_q)
    gemm_tf32<0><<<gSm, blk>>>(x, w_q, nullptr, qb);
    ln_kernel<<<M_SMALL, 256>>>(qb, ln_q_w, ln_q_b);
    // in_proj: q/k/v heads
    gemm_tf32<0><<<gSm,  blk>>>(qb,  in_w,                 in_b,        qh);
    gemm_tf32<0><<<gBig, blk>>>(key, in_w + 1024 * 1024,   in_b + 1024, kh);
    gemm_tf32<0><<<gBig, blk>>>(val, in_w + 2 * 1024 * 1024, in_b + 2048, vh);
    // attention over 2x2 patches
    attn_kernel<<<M_SMALL, 256>>>(qh, kh, vh, o);
    // out_proj -> d_out (rows already in (n, q) order)
    gemm_tf32<0><<<gSm, blk>>>(o, out_w, out_b, (float*)d_out);
}